// round 7
// baseline (speedup 1.0000x reference)
#include <cuda_runtime.h>

// VDEncoderDecoder: LSTM encoder (8->32->8->1, T=48) + decoder (1->2->2->1,
// 60 steps) + fused fc via g = fc2_w @ fc1_w.
// Thread PAIR (t, t^1) processes an element pair. f32x2 packs the two
// elements; each thread owns HALF the units (all 4 gates) of e1/e2, so
// activations and c-state are thread-local and only new-h is exchanged via
// warp shuffle (16+4 u64 per timestep). e3/decoder/fc run per element on one
// thread each. Weights pre-splat as u64 pairs in dynamic smem.

#define TPB 128
static constexpr int BATCH = 32768;
static constexpr int T = 48;

typedef unsigned long long u64;

// u64 smem offsets (pre-splat weight pairs)
static constexpr int U_E1IH = 0;      // 1024: [u*32 + g*8 + d]
static constexpr int U_E1HH = 1024;   // 4096: [u*128 + g*32 + j]
static constexpr int U_E2IH = 5120;   // 1024: [u*128 + g*32 + d]
static constexpr int U_E2HH = 6144;   // 256:  [u*32 + g*8 + j]
static constexpr int U_B1   = 6400;   // 128:  [u*4 + g]
static constexpr int U_B2   = 6528;   // 32:   [u*4 + g]
static constexpr int U_TOTAL = 6560;

// float smem offsets (after u64 region)
static constexpr int F_G  = 0;     // 720: g[t*12 + j]
static constexpr int F_CB = 720;   // 12
static constexpr int F_SM = 732;   // small scalar block (140)
static constexpr int F_TOTAL = 872;
// small block offsets (relative to F_SM)
static constexpr int S_W3IH = 0;    // 32
static constexpr int S_W3HH = 32;   // 4
static constexpr int S_B3   = 36;   // 4
static constexpr int S_D1IH = 40;   // 8
static constexpr int S_D1HH = 48;   // 16
static constexpr int S_BD1  = 64;   // 8
static constexpr int S_D2IH = 72;   // 16
static constexpr int S_D2HH = 88;   // 16
static constexpr int S_BD2  = 104;  // 8
static constexpr int S_D3IH = 112;  // 8
static constexpr int S_D3HH = 120;  // 4
static constexpr int S_BD3  = 124;  // 4

static constexpr int SMEM_BYTES = U_TOTAL * 8 + F_TOTAL * 4;  // 55968

__device__ __forceinline__ u64 fma2(u64 a, u64 b, u64 c) {
    u64 d;
    asm("fma.rn.f32x2 %0, %1, %2, %3;" : "=l"(d) : "l"(a), "l"(b), "l"(c));
    return d;
}
__device__ __forceinline__ u64 pack2(float v) {
    u64 r;
    asm("mov.b64 %0, {%1, %1};" : "=l"(r) : "f"(v));
    return r;
}
__device__ __forceinline__ u64 pack2f(float lo, float hi) {
    u64 r;
    asm("mov.b64 %0, {%1, %2};" : "=l"(r) : "f"(lo), "f"(hi));
    return r;
}
__device__ __forceinline__ void unpack2(u64 v, float& lo, float& hi) {
    asm("mov.b64 {%0, %1}, %2;" : "=f"(lo), "=f"(hi) : "l"(v));
}

__device__ __forceinline__ float sigf(float x) {
    return __fdividef(1.0f, 1.0f + __expf(-x));
}
__device__ __forceinline__ float tanhx(float x) {
    float e = __expf(2.0f * x);
    return 1.0f - __fdividef(2.0f, e + 1.0f);
}

// Small scalar LSTM cell, fully unrolled (per-element decoder path).
template<int H, int DIN>
__device__ __forceinline__ void lstm_small(
    const float* __restrict__ wih, const float* __restrict__ whh,
    const float* __restrict__ bias,
    const float (&xin)[DIN], float (&h)[H], float (&c)[H])
{
    float hn[H];
#pragma unroll
    for (int u = 0; u < H; ++u) {
        float a0 = bias[u];
        float a1 = bias[H + u];
        float a2 = bias[2 * H + u];
        float a3 = bias[3 * H + u];
#pragma unroll
        for (int d = 0; d < DIN; ++d) {
            float xv = xin[d];
            a0 = fmaf(xv, wih[u * DIN + d], a0);
            a1 = fmaf(xv, wih[(H + u) * DIN + d], a1);
            a2 = fmaf(xv, wih[(2 * H + u) * DIN + d], a2);
            a3 = fmaf(xv, wih[(3 * H + u) * DIN + d], a3);
        }
#pragma unroll
        for (int j = 0; j < H; ++j) {
            float hv = h[j];
            a0 = fmaf(hv, whh[u * H + j], a0);
            a1 = fmaf(hv, whh[(H + u) * H + j], a1);
            a2 = fmaf(hv, whh[(2 * H + u) * H + j], a2);
            a3 = fmaf(hv, whh[(3 * H + u) * H + j], a3);
        }
        float ig = sigf(a0);
        float fg = sigf(a1);
        float gg = tanhx(a2);
        float og = sigf(a3);
        float cn = fmaf(fg, c[u], ig * gg);
        c[u] = cn;
        hn[u] = og * tanhx(cn);
    }
#pragma unroll
    for (int u = 0; u < H; ++u) h[u] = hn[u];
}

__global__ void __launch_bounds__(TPB)
vd_encdec_kernel(
    const float* __restrict__ x,
    const float* __restrict__ w1ih, const float* __restrict__ w1hh, const float* __restrict__ b1,
    const float* __restrict__ w2ih, const float* __restrict__ w2hh, const float* __restrict__ b2,
    const float* __restrict__ w3ih, const float* __restrict__ w3hh, const float* __restrict__ b3,
    const float* __restrict__ d1ih, const float* __restrict__ d1hh, const float* __restrict__ bd1,
    const float* __restrict__ d2ih, const float* __restrict__ d2hh, const float* __restrict__ bd2,
    const float* __restrict__ d3ih, const float* __restrict__ d3hh, const float* __restrict__ bd3,
    const float* __restrict__ fc1w, const float* __restrict__ fc1b,
    const float* __restrict__ fc2w, const float* __restrict__ fc2b,
    float* __restrict__ out)
{
    extern __shared__ __align__(16) unsigned char dynsmem[];
    u64* swp = reinterpret_cast<u64*>(dynsmem);
    float* swf = reinterpret_cast<float*>(dynsmem + (size_t)U_TOTAL * 8);
    const int tid = threadIdx.x;

    // ---- stage pre-splat weights ----
    for (int i = tid; i < 1024; i += TPB) {
        int u = i >> 5, g = (i >> 3) & 3, d = i & 7;
        swp[U_E1IH + i] = pack2(w1ih[(g * 32 + u) * 8 + d]);
    }
    for (int i = tid; i < 4096; i += TPB) {
        int u = i >> 7, g = (i >> 5) & 3, j = i & 31;
        swp[U_E1HH + i] = pack2(w1hh[(g * 32 + u) * 32 + j]);
    }
    for (int i = tid; i < 1024; i += TPB) {
        int u = i >> 7, g = (i >> 5) & 3, d = i & 31;
        swp[U_E2IH + i] = pack2(w2ih[(g * 8 + u) * 32 + d]);
    }
    for (int i = tid; i < 256; i += TPB) {
        int u = i >> 5, g = (i >> 3) & 3, j = i & 7;
        swp[U_E2HH + i] = pack2(w2hh[(g * 8 + u) * 8 + j]);
    }
    for (int i = tid; i < 128; i += TPB) {
        int u = i >> 2, g = i & 3;
        swp[U_B1 + i] = pack2(b1[g * 32 + u]);
    }
    for (int i = tid; i < 32; i += TPB) {
        int u = i >> 2, g = i & 3;
        swp[U_B2 + i] = pack2(b2[g * 8 + u]);
    }
    // fused fc: g[t*12+j] = sum_k fc2w[j,k]*fc1w[k,t]
    for (int i = tid; i < 720; i += TPB) {
        int t = i / 12, j = i % 12;
        float a = 0.0f;
        for (int k = 0; k < 32; ++k)
            a = fmaf(fc2w[j * 32 + k], fc1w[k * 60 + t], a);
        swf[F_G + i] = a;
    }
    if (tid < 12) {
        float a = fc2b[tid];
        for (int k = 0; k < 32; ++k)
            a = fmaf(fc2w[tid * 32 + k], fc1b[k], a);
        swf[F_CB + tid] = a;
    }
    float* sws = swf + F_SM;
    for (int i = tid; i < 32; i += TPB) sws[S_W3IH + i] = w3ih[i];
    if (tid < 4)  sws[S_W3HH + tid] = w3hh[tid];
    if (tid < 4)  sws[S_B3 + tid] = b3[tid];
    if (tid < 8)  sws[S_D1IH + tid] = d1ih[tid];
    if (tid < 16) sws[S_D1HH + tid] = d1hh[tid];
    if (tid < 8)  sws[S_BD1 + tid] = bd1[tid];
    if (tid < 16) sws[S_D2IH + tid] = d2ih[tid];
    if (tid < 16) sws[S_D2HH + tid] = d2hh[tid];
    if (tid < 8)  sws[S_BD2 + tid] = bd2[tid];
    if (tid < 8)  sws[S_D3IH + tid] = d3ih[tid];
    if (tid < 4)  sws[S_D3HH + tid] = d3hh[tid];
    if (tid < 4)  sws[S_BD3 + tid] = bd3[tid];
    __syncthreads();

    const int gtid = blockIdx.x * TPB + tid;     // = my element id
    const bool even = (tid & 1) == 0;            // even thread = element pair lo
    const float* xb = x + (size_t)gtid * (T * 8);
    const int ub1 = (tid & 1) * 16;              // my e1 units: ub1..ub1+15
    const int ub2 = (tid & 1) * 4;               // my e2 units: ub2..ub2+3

    u64 hp1[32];      // full packed h1 (registers; statically indexed)
    u64 hp2[8];       // full packed h2
    u64 c1p[16];      // my units' c (local ok)
    u64 c2p[4];
    u64 hn1l[16], hn2l[4];
    float h3[1], c3[1];
    float hd1[2], cd1[2], hd2[2], cd2[2], hd3[1], cd3[1];
    float acc12[12];

#pragma unroll
    for (int i = 0; i < 32; ++i) hp1[i] = 0ULL;
#pragma unroll
    for (int i = 0; i < 16; ++i) c1p[i] = 0ULL;
#pragma unroll
    for (int i = 0; i < 8; ++i) hp2[i] = 0ULL;
#pragma unroll
    for (int i = 0; i < 4; ++i) c2p[i] = 0ULL;
    h3[0] = 0.0f; c3[0] = 0.0f;
#pragma unroll
    for (int i = 0; i < 2; ++i) { hd1[i] = 0.0f; cd1[i] = 0.0f; hd2[i] = 0.0f; cd2[i] = 0.0f; }
    hd3[0] = 0.0f; cd3[0] = 0.0f;
#pragma unroll
    for (int i = 0; i < 12; ++i) acc12[i] = 0.0f;

    // ---- fused steps t = 0..47 ----
#pragma unroll 1
    for (int t = 0; t < T; ++t) {
        // my element's x; exchange with partner to build element-pair packs
        float4 xa = *reinterpret_cast<const float4*>(xb + t * 8);
        float4 xc = *reinterpret_cast<const float4*>(xb + t * 8 + 4);
        float xm[8] = { xa.x, xa.y, xa.z, xa.w, xc.x, xc.y, xc.z, xc.w };
        u64 xp[8];
#pragma unroll
        for (int d = 0; d < 8; ++d) {
            float xo = __shfl_xor_sync(0xFFFFFFFFu, xm[d], 1);
            float e0 = even ? xm[d] : xo;
            float e1 = even ? xo : xm[d];
            xp[d] = pack2f(e0, e1);
        }

        // ---- e1: my 16 units, all 4 gates ----
#pragma unroll 2
        for (int uu = 0; uu < 16; ++uu) {
            int u = ub1 + uu;
            u64 a0 = swp[U_B1 + u * 4 + 0];
            u64 a1 = swp[U_B1 + u * 4 + 1];
            u64 a2 = swp[U_B1 + u * 4 + 2];
            u64 a3 = swp[U_B1 + u * 4 + 3];
            const ulonglong2* wi = reinterpret_cast<const ulonglong2*>(swp + U_E1IH + u * 32);
#pragma unroll
            for (int d = 0; d < 4; ++d) {
                ulonglong2 q0 = wi[d], q1 = wi[4 + d], q2 = wi[8 + d], q3 = wi[12 + d];
                a0 = fma2(q0.x, xp[2 * d], a0);
                a1 = fma2(q1.x, xp[2 * d], a1);
                a2 = fma2(q2.x, xp[2 * d], a2);
                a3 = fma2(q3.x, xp[2 * d], a3);
                a0 = fma2(q0.y, xp[2 * d + 1], a0);
                a1 = fma2(q1.y, xp[2 * d + 1], a1);
                a2 = fma2(q2.y, xp[2 * d + 1], a2);
                a3 = fma2(q3.y, xp[2 * d + 1], a3);
            }
            const ulonglong2* wh = reinterpret_cast<const ulonglong2*>(swp + U_E1HH + u * 128);
#pragma unroll
            for (int j = 0; j < 16; ++j) {
                ulonglong2 q0 = wh[j], q1 = wh[16 + j], q2 = wh[32 + j], q3 = wh[48 + j];
                a0 = fma2(q0.x, hp1[2 * j], a0);
                a1 = fma2(q1.x, hp1[2 * j], a1);
                a2 = fma2(q2.x, hp1[2 * j], a2);
                a3 = fma2(q3.x, hp1[2 * j], a3);
                a0 = fma2(q0.y, hp1[2 * j + 1], a0);
                a1 = fma2(q1.y, hp1[2 * j + 1], a1);
                a2 = fma2(q2.y, hp1[2 * j + 1], a2);
                a3 = fma2(q3.y, hp1[2 * j + 1], a3);
            }
            float iA, iB, fA, fB, gA, gB, oA, oB, cA0, cB0;
            unpack2(a0, iA, iB);
            unpack2(a1, fA, fB);
            unpack2(a2, gA, gB);
            unpack2(a3, oA, oB);
            unpack2(c1p[uu], cA0, cB0);
            float cA = fmaf(sigf(fA), cA0, sigf(iA) * tanhx(gA));
            float cB = fmaf(sigf(fB), cB0, sigf(iB) * tanhx(gB));
            c1p[uu] = pack2f(cA, cB);
            hn1l[uu] = pack2f(sigf(oA) * tanhx(cA), sigf(oB) * tanhx(cB));
        }
        // exchange new h1 halves with partner (units: even owns 0..15, odd 16..31)
#pragma unroll
        for (int k = 0; k < 16; ++k) {
            u64 mine = hn1l[k];
            u64 other = __shfl_xor_sync(0xFFFFFFFFu, mine, 1);
            hp1[k]      = even ? mine : other;
            hp1[16 + k] = even ? other : mine;
        }

        // ---- e2: my 4 units ----
#pragma unroll 2
        for (int uu = 0; uu < 4; ++uu) {
            int u = ub2 + uu;
            u64 a0 = swp[U_B2 + u * 4 + 0];
            u64 a1 = swp[U_B2 + u * 4 + 1];
            u64 a2 = swp[U_B2 + u * 4 + 2];
            u64 a3 = swp[U_B2 + u * 4 + 3];
            const ulonglong2* wi = reinterpret_cast<const ulonglong2*>(swp + U_E2IH + u * 128);
#pragma unroll
            for (int d = 0; d < 16; ++d) {
                ulonglong2 q0 = wi[d], q1 = wi[16 + d], q2 = wi[32 + d], q3 = wi[48 + d];
                a0 = fma2(q0.x, hp1[2 * d], a0);
                a1 = fma2(q1.x, hp1[2 * d], a1);
                a2 = fma2(q2.x, hp1[2 * d], a2);
                a3 = fma2(q3.x, hp1[2 * d], a3);
                a0 = fma2(q0.y, hp1[2 * d + 1], a0);
                a1 = fma2(q1.y, hp1[2 * d + 1], a1);
                a2 = fma2(q2.y, hp1[2 * d + 1], a2);
                a3 = fma2(q3.y, hp1[2 * d + 1], a3);
            }
            const ulonglong2* wh = reinterpret_cast<const ulonglong2*>(swp + U_E2HH + u * 32);
#pragma unroll
            for (int j = 0; j < 4; ++j) {
                ulonglong2 q0 = wh[j], q1 = wh[4 + j], q2 = wh[8 + j], q3 = wh[12 + j];
                a0 = fma2(q0.x, hp2[2 * j], a0);
                a1 = fma2(q1.x, hp2[2 * j], a1);
                a2 = fma2(q2.x, hp2[2 * j], a2);
                a3 = fma2(q3.x, hp2[2 * j], a3);
                a0 = fma2(q0.y, hp2[2 * j + 1], a0);
                a1 = fma2(q1.y, hp2[2 * j + 1], a1);
                a2 = fma2(q2.y, hp2[2 * j + 1], a2);
                a3 = fma2(q3.y, hp2[2 * j + 1], a3);
            }
            float iA, iB, fA, fB, gA, gB, oA, oB, cA0, cB0;
            unpack2(a0, iA, iB);
            unpack2(a1, fA, fB);
            unpack2(a2, gA, gB);
            unpack2(a3, oA, oB);
            unpack2(c2p[uu], cA0, cB0);
            float cA = fmaf(sigf(fA), cA0, sigf(iA) * tanhx(gA));
            float cB = fmaf(sigf(fB), cB0, sigf(iB) * tanhx(gB));
            c2p[uu] = pack2f(cA, cB);
            hn2l[uu] = pack2f(sigf(oA) * tanhx(cA), sigf(oB) * tanhx(cB));
        }
        // exchange new h2 halves
#pragma unroll
        for (int k = 0; k < 4; ++k) {
            u64 mine = hn2l[k];
            u64 other = __shfl_xor_sync(0xFFFFFFFFu, mine, 1);
            hp2[k]     = even ? mine : other;
            hp2[4 + k] = even ? other : mine;
        }

        // ---- e3 + decoder for MY element (scalar) ----
        float h2me[8];
#pragma unroll
        for (int j = 0; j < 8; ++j) {
            float lo, hi;
            unpack2(hp2[j], lo, hi);
            h2me[j] = even ? lo : hi;
        }
        lstm_small<1, 8>(sws + S_W3IH, sws + S_W3HH, sws + S_B3, h2me, h3, c3);
        float dv[1] = { h3[0] };
        lstm_small<2, 1>(sws + S_D1IH, sws + S_D1HH, sws + S_BD1, dv, hd1, cd1);
        lstm_small<2, 2>(sws + S_D2IH, sws + S_D2HH, sws + S_BD2, hd1, hd2, cd2);
        lstm_small<1, 2>(sws + S_D3IH, sws + S_D3HH, sws + S_BD3, hd2, hd3, cd3);

        float y = hd3[0];
        const float* gr = swf + F_G + t * 12;
#pragma unroll
        for (int j = 0; j < 12; ++j) acc12[j] = fmaf(y, gr[j], acc12[j]);
    }

    // ---- aux steps t = 48..59: decoder input = x[me, t-12, 4] ----
#pragma unroll 1
    for (int t = T; t < 60; ++t) {
        float dv[1] = { xb[(t - 12) * 8 + 4] };
        lstm_small<2, 1>(sws + S_D1IH, sws + S_D1HH, sws + S_BD1, dv, hd1, cd1);
        lstm_small<2, 2>(sws + S_D2IH, sws + S_D2HH, sws + S_BD2, hd1, hd2, cd2);
        lstm_small<1, 2>(sws + S_D3IH, sws + S_D3HH, sws + S_BD3, hd2, hd3, cd3);

        float y = hd3[0];
        const float* gr = swf + F_G + t * 12;
#pragma unroll
        for (int j = 0; j < 12; ++j) acc12[j] = fmaf(y, gr[j], acc12[j]);
    }

    // ---- epilogue: out[me] = acc12 + cb ----
    float r[12];
#pragma unroll
    for (int j = 0; j < 12; ++j) r[j] = acc12[j] + swf[F_CB + j];
    float4* op = reinterpret_cast<float4*>(out + (size_t)gtid * 12);
    op[0] = make_float4(r[0], r[1], r[2], r[3]);
    op[1] = make_float4(r[4], r[5], r[6], r[7]);
    op[2] = make_float4(r[8], r[9], r[10], r[11]);
}

extern "C" void kernel_launch(void* const* d_in, const int* in_sizes, int n_in,
                              void* d_out, int out_size) {
    (void)in_sizes; (void)n_in; (void)out_size;
    const float* x    = (const float*)d_in[0];
    const float* w1ih = (const float*)d_in[1];
    const float* w1hh = (const float*)d_in[2];
    const float* b1   = (const float*)d_in[3];
    const float* w2ih = (const float*)d_in[4];
    const float* w2hh = (const float*)d_in[5];
    const float* b2   = (const float*)d_in[6];
    const float* w3ih = (const float*)d_in[7];
    const float* w3hh = (const float*)d_in[8];
    const float* b3   = (const float*)d_in[9];
    const float* d1ih = (const float*)d_in[10];
    const float* d1hh = (const float*)d_in[11];
    const float* bd1  = (const float*)d_in[12];
    const float* d2ih = (const float*)d_in[13];
    const float* d2hh = (const float*)d_in[14];
    const float* bd2  = (const float*)d_in[15];
    const float* d3ih = (const float*)d_in[16];
    const float* d3hh = (const float*)d_in[17];
    const float* bd3  = (const float*)d_in[18];
    const float* fc1w = (const float*)d_in[19];
    const float* fc1b = (const float*)d_in[20];
    const float* fc2w = (const float*)d_in[21];
    const float* fc2b = (const float*)d_in[22];
    float* out = (float*)d_out;

    static int smem_configured = 0;
    cudaFuncSetAttribute(vd_encdec_kernel,
                         cudaFuncAttributeMaxDynamicSharedMemorySize, SMEM_BYTES);
    (void)smem_configured;

    dim3 grid(BATCH / TPB);
    dim3 block(TPB);
    vd_encdec_kernel<<<grid, block, SMEM_BYTES>>>(
        x, w1ih, w1hh, b1, w2ih, w2hh, b2, w3ih, w3hh, b3,
        d1ih, d1hh, bd1, d2ih, d2hh, bd2, d3ih, d3hh, bd3,
        fc1w, fc1b, fc2w, fc2b, out);
}

// round 8
// speedup vs baseline: 1.4595x; 1.4595x over previous
#include <cuda_runtime.h>

// VDEncoderDecoder: stacked LSTM encoder (8->32->8->1, T=48) + decoder
// (1->2->2->1, 60 steps) + fused fc via g = fc2_w @ fc1_w.
// One thread per batch element (R2 architecture). Fixes vs R2:
//  - TPB=32, grid=1024: ~7 warps on EVERY SM (R2's 256 CTAs left a 2-vs-1
//    CTA imbalance across 148 SMs).
//  - explicit float4 weight loads (LDS.128): 4 MACs per load -> issue-slot
//    count drops below the FMA-pipe floor.

#define TPB 32
static constexpr int BATCH = 32768;
static constexpr int T = 48;

// shared-memory float offsets
static constexpr int OFF_W1IH = 0;       // 128x8   = 1024
static constexpr int OFF_W1HH = 1024;    // 128x32  = 4096
static constexpr int OFF_B1   = 5120;    // 128
static constexpr int OFF_W2IH = 5248;    // 32x32   = 1024
static constexpr int OFF_W2HH = 6272;    // 32x8    = 256
static constexpr int OFF_B2   = 6528;    // 32
static constexpr int OFF_W3IH = 6560;    // 32
static constexpr int OFF_W3HH = 6592;    // 4
static constexpr int OFF_B3   = 6596;    // 4
static constexpr int OFF_D1IH = 6600;    // 8
static constexpr int OFF_D1HH = 6608;    // 16
static constexpr int OFF_BD1  = 6624;    // 8
static constexpr int OFF_D2IH = 6632;    // 16
static constexpr int OFF_D2HH = 6648;    // 16
static constexpr int OFF_BD2  = 6664;    // 8
static constexpr int OFF_D3IH = 6672;    // 8
static constexpr int OFF_D3HH = 6680;    // 4
static constexpr int OFF_BD3  = 6684;    // 4
static constexpr int OFF_G    = 6688;    // 60x12 = 720 (g[t*12+j] = fc2@fc1)
static constexpr int OFF_CB   = 7408;    // 12          (fc2b + fc2w@fc1b)
static constexpr int SMEM_FLOATS = 7424; // 29696 B -> 7 CTAs/SM fit in 228KB

__device__ __forceinline__ float sigf(float x) {
    return __fdividef(1.0f, 1.0f + __expf(-x));
}
__device__ __forceinline__ float tanhx(float x) {
    float e = __expf(2.0f * x);
    return 1.0f - __fdividef(2.0f, e + 1.0f);
}

// Big LSTM cell: runtime unit loop (bounded registers), explicit float4
// weight loads, 4 independent accumulator chains.
template<int H, int DIN>
__device__ __forceinline__ void lstm_big(
    const float* __restrict__ wih, const float* __restrict__ whh,
    const float* __restrict__ bias,
    const float (&xin)[DIN], float (&h)[H], float* __restrict__ c)
{
    float hn[H];
#pragma unroll 1
    for (int u = 0; u < H; ++u) {
        float a0 = bias[u];
        float a1 = bias[H + u];
        float a2 = bias[2 * H + u];
        float a3 = bias[3 * H + u];
        const float4* w0 = reinterpret_cast<const float4*>(wih + u * DIN);
        const float4* w1 = reinterpret_cast<const float4*>(wih + (H + u) * DIN);
        const float4* w2 = reinterpret_cast<const float4*>(wih + (2 * H + u) * DIN);
        const float4* w3 = reinterpret_cast<const float4*>(wih + (3 * H + u) * DIN);
#pragma unroll
        for (int d = 0; d < DIN / 4; ++d) {
            float4 q0 = w0[d], q1 = w1[d], q2 = w2[d], q3 = w3[d];
            float xv0 = xin[4 * d + 0], xv1 = xin[4 * d + 1];
            float xv2 = xin[4 * d + 2], xv3 = xin[4 * d + 3];
            a0 = fmaf(xv0, q0.x, a0);
            a1 = fmaf(xv0, q1.x, a1);
            a2 = fmaf(xv0, q2.x, a2);
            a3 = fmaf(xv0, q3.x, a3);
            a0 = fmaf(xv1, q0.y, a0);
            a1 = fmaf(xv1, q1.y, a1);
            a2 = fmaf(xv1, q2.y, a2);
            a3 = fmaf(xv1, q3.y, a3);
            a0 = fmaf(xv2, q0.z, a0);
            a1 = fmaf(xv2, q1.z, a1);
            a2 = fmaf(xv2, q2.z, a2);
            a3 = fmaf(xv2, q3.z, a3);
            a0 = fmaf(xv3, q0.w, a0);
            a1 = fmaf(xv3, q1.w, a1);
            a2 = fmaf(xv3, q2.w, a2);
            a3 = fmaf(xv3, q3.w, a3);
        }
        const float4* v0 = reinterpret_cast<const float4*>(whh + u * H);
        const float4* v1 = reinterpret_cast<const float4*>(whh + (H + u) * H);
        const float4* v2 = reinterpret_cast<const float4*>(whh + (2 * H + u) * H);
        const float4* v3 = reinterpret_cast<const float4*>(whh + (3 * H + u) * H);
#pragma unroll
        for (int j = 0; j < H / 4; ++j) {
            float4 q0 = v0[j], q1 = v1[j], q2 = v2[j], q3 = v3[j];
            float hv0 = h[4 * j + 0], hv1 = h[4 * j + 1];
            float hv2 = h[4 * j + 2], hv3 = h[4 * j + 3];
            a0 = fmaf(hv0, q0.x, a0);
            a1 = fmaf(hv0, q1.x, a1);
            a2 = fmaf(hv0, q2.x, a2);
            a3 = fmaf(hv0, q3.x, a3);
            a0 = fmaf(hv1, q0.y, a0);
            a1 = fmaf(hv1, q1.y, a1);
            a2 = fmaf(hv1, q2.y, a2);
            a3 = fmaf(hv1, q3.y, a3);
            a0 = fmaf(hv2, q0.z, a0);
            a1 = fmaf(hv2, q1.z, a1);
            a2 = fmaf(hv2, q2.z, a2);
            a3 = fmaf(hv2, q3.z, a3);
            a0 = fmaf(hv3, q0.w, a0);
            a1 = fmaf(hv3, q1.w, a1);
            a2 = fmaf(hv3, q2.w, a2);
            a3 = fmaf(hv3, q3.w, a3);
        }
        float ig = sigf(a0);
        float fg = sigf(a1);
        float gg = tanhx(a2);
        float og = sigf(a3);
        float cn = fmaf(fg, c[u], ig * gg);
        c[u] = cn;
        hn[u] = og * tanhx(cn);
    }
#pragma unroll
    for (int u = 0; u < H; ++u) h[u] = hn[u];
}

// Small scalar LSTM cell, fully unrolled.
template<int H, int DIN>
__device__ __forceinline__ void lstm_small(
    const float* __restrict__ wih, const float* __restrict__ whh,
    const float* __restrict__ bias,
    const float (&xin)[DIN], float (&h)[H], float (&c)[H])
{
    float hn[H];
#pragma unroll
    for (int u = 0; u < H; ++u) {
        float a0 = bias[u];
        float a1 = bias[H + u];
        float a2 = bias[2 * H + u];
        float a3 = bias[3 * H + u];
#pragma unroll
        for (int d = 0; d < DIN; ++d) {
            float xv = xin[d];
            a0 = fmaf(xv, wih[u * DIN + d], a0);
            a1 = fmaf(xv, wih[(H + u) * DIN + d], a1);
            a2 = fmaf(xv, wih[(2 * H + u) * DIN + d], a2);
            a3 = fmaf(xv, wih[(3 * H + u) * DIN + d], a3);
        }
#pragma unroll
        for (int j = 0; j < H; ++j) {
            float hv = h[j];
            a0 = fmaf(hv, whh[u * H + j], a0);
            a1 = fmaf(hv, whh[(H + u) * H + j], a1);
            a2 = fmaf(hv, whh[(2 * H + u) * H + j], a2);
            a3 = fmaf(hv, whh[(3 * H + u) * H + j], a3);
        }
        float ig = sigf(a0);
        float fg = sigf(a1);
        float gg = tanhx(a2);
        float og = sigf(a3);
        float cn = fmaf(fg, c[u], ig * gg);
        c[u] = cn;
        hn[u] = og * tanhx(cn);
    }
#pragma unroll
    for (int u = 0; u < H; ++u) h[u] = hn[u];
}

__global__ void __launch_bounds__(TPB)
vd_encdec_kernel(
    const float* __restrict__ x,
    const float* __restrict__ w1ih, const float* __restrict__ w1hh, const float* __restrict__ b1,
    const float* __restrict__ w2ih, const float* __restrict__ w2hh, const float* __restrict__ b2,
    const float* __restrict__ w3ih, const float* __restrict__ w3hh, const float* __restrict__ b3,
    const float* __restrict__ d1ih, const float* __restrict__ d1hh, const float* __restrict__ bd1,
    const float* __restrict__ d2ih, const float* __restrict__ d2hh, const float* __restrict__ bd2,
    const float* __restrict__ d3ih, const float* __restrict__ d3hh, const float* __restrict__ bd3,
    const float* __restrict__ fc1w, const float* __restrict__ fc1b,
    const float* __restrict__ fc2w, const float* __restrict__ fc2b,
    float* __restrict__ out)
{
    __shared__ __align__(16) float sw[SMEM_FLOATS];
    const int tid = threadIdx.x;

    for (int i = tid; i < 1024; i += TPB) sw[OFF_W1IH + i] = w1ih[i];
    for (int i = tid; i < 4096; i += TPB) sw[OFF_W1HH + i] = w1hh[i];
    for (int i = tid; i < 128;  i += TPB) sw[OFF_B1   + i] = b1[i];
    for (int i = tid; i < 1024; i += TPB) sw[OFF_W2IH + i] = w2ih[i];
    for (int i = tid; i < 256;  i += TPB) sw[OFF_W2HH + i] = w2hh[i];
    for (int i = tid; i < 32;   i += TPB) sw[OFF_B2   + i] = b2[i];
    for (int i = tid; i < 32;   i += TPB) sw[OFF_W3IH + i] = w3ih[i];
    if (tid < 4)  sw[OFF_W3HH + tid] = w3hh[tid];
    if (tid < 4)  sw[OFF_B3   + tid] = b3[tid];
    if (tid < 8)  sw[OFF_D1IH + tid] = d1ih[tid];
    if (tid < 16) sw[OFF_D1HH + tid] = d1hh[tid];
    if (tid < 8)  sw[OFF_BD1 + tid] = bd1[tid];
    if (tid < 16) sw[OFF_D2IH + tid] = d2ih[tid];
    if (tid < 16) sw[OFF_D2HH + tid] = d2hh[tid];
    if (tid < 8)  sw[OFF_BD2 + tid] = bd2[tid];
    if (tid < 8)  sw[OFF_D3IH + tid] = d3ih[tid];
    if (tid < 4)  sw[OFF_D3HH + tid] = d3hh[tid];
    if (tid < 4)  sw[OFF_BD3 + tid] = bd3[tid];
    // fused fc: g[t*12+j] = sum_k fc2w[j,k] * fc1w[k,t]
    for (int i = tid; i < 720; i += TPB) {
        int t = i / 12, j = i % 12;
        float a = 0.0f;
        for (int k = 0; k < 32; ++k)
            a = fmaf(fc2w[j * 32 + k], fc1w[k * 60 + t], a);
        sw[OFF_G + i] = a;
    }
    if (tid < 12) {
        float a = fc2b[tid];
        for (int k = 0; k < 32; ++k)
            a = fmaf(fc2w[tid * 32 + k], fc1b[k], a);
        sw[OFF_CB + tid] = a;
    }
    __syncthreads();

    const int b = blockIdx.x * TPB + tid;
    const float* xb = x + (size_t)b * (T * 8);

    float h1[32], c1[32], h2[8], c2[8], h3[1], c3[1];
    float hd1[2], cd1[2], hd2[2], cd2[2], hd3[1], cd3[1];
    float acc[12];
#pragma unroll
    for (int i = 0; i < 32; ++i) { h1[i] = 0.0f; c1[i] = 0.0f; }
#pragma unroll
    for (int i = 0; i < 8; ++i) { h2[i] = 0.0f; c2[i] = 0.0f; }
    h3[0] = 0.0f; c3[0] = 0.0f;
#pragma unroll
    for (int i = 0; i < 2; ++i) { hd1[i] = 0.0f; cd1[i] = 0.0f; hd2[i] = 0.0f; cd2[i] = 0.0f; }
    hd3[0] = 0.0f; cd3[0] = 0.0f;
#pragma unroll
    for (int i = 0; i < 12; ++i) acc[i] = 0.0f;

    // ---- fused steps t = 0..47: encoder + decoder + fc accumulation ----
#pragma unroll 1
    for (int t = 0; t < T; ++t) {
        float4 xa = *reinterpret_cast<const float4*>(xb + t * 8);
        float4 xc = *reinterpret_cast<const float4*>(xb + t * 8 + 4);
        float xr[8] = { xa.x, xa.y, xa.z, xa.w, xc.x, xc.y, xc.z, xc.w };

        lstm_big<32, 8>(sw + OFF_W1IH, sw + OFF_W1HH, sw + OFF_B1, xr, h1, c1);
        lstm_big<8, 32>(sw + OFF_W2IH, sw + OFF_W2HH, sw + OFF_B2, h1, h2, c2);
        lstm_small<1, 8>(sw + OFF_W3IH, sw + OFF_W3HH, sw + OFF_B3, h2, h3, c3);

        float dv[1] = { h3[0] };
        lstm_small<2, 1>(sw + OFF_D1IH, sw + OFF_D1HH, sw + OFF_BD1, dv, hd1, cd1);
        lstm_small<2, 2>(sw + OFF_D2IH, sw + OFF_D2HH, sw + OFF_BD2, hd1, hd2, cd2);
        lstm_small<1, 2>(sw + OFF_D3IH, sw + OFF_D3HH, sw + OFF_BD3, hd2, hd3, cd3);

        float y = hd3[0];
        const float* gr = sw + OFF_G + t * 12;
#pragma unroll
        for (int j = 0; j < 12; ++j) acc[j] = fmaf(y, gr[j], acc[j]);
    }

    // ---- aux steps t = 48..59: decoder input = x[b, t-12, 4] ----
#pragma unroll 1
    for (int t = T; t < 60; ++t) {
        float dv[1] = { xb[(t - 12) * 8 + 4] };
        lstm_small<2, 1>(sw + OFF_D1IH, sw + OFF_D1HH, sw + OFF_BD1, dv, hd1, cd1);
        lstm_small<2, 2>(sw + OFF_D2IH, sw + OFF_D2HH, sw + OFF_BD2, hd1, hd2, cd2);
        lstm_small<1, 2>(sw + OFF_D3IH, sw + OFF_D3HH, sw + OFF_BD3, hd2, hd3, cd3);

        float y = hd3[0];
        const float* gr = sw + OFF_G + t * 12;
#pragma unroll
        for (int j = 0; j < 12; ++j) acc[j] = fmaf(y, gr[j], acc[j]);
    }

    // ---- epilogue ----
    float r[12];
#pragma unroll
    for (int j = 0; j < 12; ++j) r[j] = acc[j] + sw[OFF_CB + j];
    float4* op = reinterpret_cast<float4*>(out + (size_t)b * 12);
    op[0] = make_float4(r[0], r[1], r[2], r[3]);
    op[1] = make_float4(r[4], r[5], r[6], r[7]);
    op[2] = make_float4(r[8], r[9], r[10], r[11]);
}

extern "C" void kernel_launch(void* const* d_in, const int* in_sizes, int n_in,
                              void* d_out, int out_size) {
    (void)in_sizes; (void)n_in; (void)out_size;
    const float* x    = (const float*)d_in[0];
    const float* w1ih = (const float*)d_in[1];
    const float* w1hh = (const float*)d_in[2];
    const float* b1   = (const float*)d_in[3];
    const float* w2ih = (const float*)d_in[4];
    const float* w2hh = (const float*)d_in[5];
    const float* b2   = (const float*)d_in[6];
    const float* w3ih = (const float*)d_in[7];
    const float* w3hh = (const float*)d_in[8];
    const float* b3   = (const float*)d_in[9];
    const float* d1ih = (const float*)d_in[10];
    const float* d1hh = (const float*)d_in[11];
    const float* bd1  = (const float*)d_in[12];
    const float* d2ih = (const float*)d_in[13];
    const float* d2hh = (const float*)d_in[14];
    const float* bd2  = (const float*)d_in[15];
    const float* d3ih = (const float*)d_in[16];
    const float* d3hh = (const float*)d_in[17];
    const float* bd3  = (const float*)d_in[18];
    const float* fc1w = (const float*)d_in[19];
    const float* fc1b = (const float*)d_in[20];
    const float* fc2w = (const float*)d_in[21];
    const float* fc2b = (const float*)d_in[22];
    float* out = (float*)d_out;

    dim3 grid(BATCH / TPB);
    dim3 block(TPB);
    vd_encdec_kernel<<<grid, block>>>(
        x, w1ih, w1hh, b1, w2ih, w2hh, b2, w3ih, w3hh, b3,
        d1ih, d1hh, bd1, d2ih, d2hh, bd2, d3ih, d3hh, bd3,
        fc1w, fc1b, fc2w, fc2b, out);
}